// round 2
// baseline (speedup 1.0000x reference)
#include <cuda_runtime.h>
#include <math.h>

#define HH 512
#define WW 512
#define AA 180
#define PW 514              // padded image dim: rows/cols 0..513, zero border
#define RSTRIP 22           // r0 rows handled per strip
#define NSTRIPS 24          // ceil(513 / 22)
#define NSPLIT 2            // blocks per angle (strip halves)
#define SROWS (RSTRIP + 1)  // smem rows per strip (overlap 1)
#define SSTRIDE 517         // smem row stride (odd, conflict-friendly)

// Scratch (device globals; no allocation allowed):
__device__ float  g_pimg[PW * PW];   // padded image
__device__ float  g_pT[PW * PW];     // padded transposed image
__device__ float  g_sino[AA * WW];   // radon accumulator
__device__ double g_acc[2];          // [0]=sum sq proj diff, [1]=sum tv
__device__ unsigned g_cnt;           // loss-block completion counter

// ---------------------------------------------------------------------------
// Kernel 1: build padded + padded-transposed images; zero accumulators.
// g_pimg[r][c] = pred[r-1][c-1] for r,c in [1,512], else 0. g_pT = transpose.
// ---------------------------------------------------------------------------
__global__ void prep_kernel(const float* __restrict__ pred) {
    const int idx = blockIdx.x * blockDim.x + threadIdx.x;
    const int total = PW * PW;
    if (idx < total) {
        const int r = idx / PW;
        const int c = idx - r * PW;
        float a = 0.0f, b = 0.0f;
        if (r >= 1 && r <= HH && c >= 1 && c <= WW) {
            a = pred[(r - 1) * WW + (c - 1)];
            b = pred[(c - 1) * WW + (r - 1)];
        }
        g_pimg[idx] = a;
        g_pT[idx]   = b;
    }
    if (idx < AA * WW) g_sino[idx] = 0.0f;
    if (idx == 0) { g_acc[0] = 0.0; g_acc[1] = 0.0; g_cnt = 0u; }
}

// ---------------------------------------------------------------------------
// Kernel 2: strip-driven radon. blockIdx.x = angle, blockIdx.y = strip half.
// Effective coords (possibly transposed so |d(row)/dh| >= 0.707):
//   iyE = by + c*v,  ixE = bx + d*v,  v = h - 255.5
// Sample's padded top row r0 = floor(iyE)+1; strip s owns r0 in [22s, 22s+21].
// Thread = sinogram bin w; accumulates over all its strips into a register.
// ---------------------------------------------------------------------------
__global__ __launch_bounds__(512) void radon_kernel(const float* __restrict__ angles) {
    __shared__ float tile[SROWS * SSTRIDE];   // 47,564 B

    const int a = blockIdx.x;
    const int w = threadIdx.x;

    const float ang = angles[a];
    const float sn = sinf(ang);
    const float cs = cosf(ang);
    const bool  swp = fabsf(sn) > fabsf(cs);

    const float c  = swp ? -sn : cs;                     // d(iyE)/dh, |c| >= 0.7071
    const float d  = swp ?  cs : -sn;                    // d(ixE)/dh
    const float u  = (float)w + 0.5f - 256.0f;
    const float by = fmaf(swp ? cs : sn, u, 255.5f);     // iyE at v=0
    const float bx = fmaf(swp ? sn : cs, u, 255.5f);     // ixE at v=0
    const float* __restrict__ img = swp ? g_pT : g_pimg;

    const float invc  = 1.0f / c;
    const int   trips = (int)((float)RSTRIP * fabsf(invc)) + 3;   // uniform per angle

    float acc = 0.0f;
    const int s0 = blockIdx.y * (NSTRIPS / NSPLIT);
    const int s1 = s0 + (NSTRIPS / NSPLIT);

    for (int s = s0; s < s1; s++) {
        const int rbase = s * RSTRIP;

        // Load padded rows [rbase, rbase+RSTRIP] into SMEM (coalesced).
        for (int t = threadIdx.x; t < SROWS * PW; t += 512) {
            const int rr = t / PW;
            const int cc = t - rr * PW;
            const int gr = rbase + rr;
            tile[rr * SSTRIDE + cc] = (gr < PW) ? img[gr * PW + cc] : 0.0f;
        }
        __syncthreads();

        // h-window: need iyE in [rbase-1, rbase+RSTRIP-1)
        const float t0 = ((float)(rbase - 1)          - by) * invc;
        const float t1 = ((float)(rbase + RSTRIP - 1) - by) * invc;
        const float hlo = fminf(t0, t1) + 255.5f;
        const int   h0  = (int)floorf(hlo);
        const int   rcap = (513 - rbase < RSTRIP) ? (513 - rbase) : RSTRIP;

        const float v0  = (float)h0 - 255.5f;
        const float iy0 = fmaf(c, v0, by);
        const float ix0 = fmaf(d, v0, bx);

        #pragma unroll 4
        for (int k = 0; k < trips; k++) {
            const float kf = (float)k;
            const float iy = fmaf(kf, c, iy0);
            const float ix = fmaf(kf, d, ix0);
            const float fy = floorf(iy);
            const float fx = floorf(ix);
            const int   yp = (int)fy + 1 - rbase;     // strip-local top row
            const int   xp = (int)fx + 1;             // padded column
            const float wy = iy - fy;
            const float wx = ix - fx;
            const unsigned hu = (unsigned)(h0 + k);
            if ((unsigned)yp < (unsigned)rcap && (unsigned)xp <= 512u && hu < 512u) {
                const float* p = &tile[yp * SSTRIDE + xp];
                const float v00 = p[0],       v01 = p[1];
                const float v10 = p[SSTRIDE], v11 = p[SSTRIDE + 1];
                const float top = fmaf(wx, v01 - v00, v00);
                const float bot = fmaf(wx, v11 - v10, v10);
                acc += fmaf(wy, bot - top, top);
            }
        }
        __syncthreads();   // before next strip overwrites SMEM
    }
    atomicAdd(&g_sino[a * WW + w], acc);
}

// ---------------------------------------------------------------------------
// Kernel 3: fused MSE + TV reduction + finalize (last block writes out).
// ---------------------------------------------------------------------------
__global__ void loss_kernel(const float* __restrict__ pred,
                            const float* __restrict__ sino_tgt,
                            float* __restrict__ out) {
    const int tid    = blockIdx.x * blockDim.x + threadIdx.x;
    const int stride = gridDim.x * blockDim.x;

    float lp = 0.0f;
    for (int i = tid; i < AA * WW; i += stride) {
        const float df = g_sino[i] - sino_tgt[i];
        lp = fmaf(df, df, lp);
    }

    float lt = 0.0f;
    const int TVW = WW - 1, TVH = HH - 1;
    for (int i = tid; i < TVH * TVW; i += stride) {
        const int y = i / TVW;
        const int x = i - y * TVW;
        const float p  = pred[y * WW + x];
        const float dx = pred[y * WW + x + 1] - p;
        const float dy = pred[(y + 1) * WW + x] - p;
        lt += sqrtf(fmaf(dx, dx, fmaf(dy, dy, 1e-8f)));
    }

    for (int off = 16; off > 0; off >>= 1) {
        lp += __shfl_down_sync(0xFFFFFFFFu, lp, off);
        lt += __shfl_down_sync(0xFFFFFFFFu, lt, off);
    }
    __shared__ float s_lp[32], s_lt[32];
    const int lane = threadIdx.x & 31;
    const int warp = threadIdx.x >> 5;
    if (lane == 0) { s_lp[warp] = lp; s_lt[warp] = lt; }
    __syncthreads();
    const int nwarps = blockDim.x >> 5;
    if (warp == 0) {
        lp = (lane < nwarps) ? s_lp[lane] : 0.0f;
        lt = (lane < nwarps) ? s_lt[lane] : 0.0f;
        for (int off = 16; off > 0; off >>= 1) {
            lp += __shfl_down_sync(0xFFFFFFFFu, lp, off);
            lt += __shfl_down_sync(0xFFFFFFFFu, lt, off);
        }
        if (lane == 0) {
            atomicAdd(&g_acc[0], (double)lp);
            atomicAdd(&g_acc[1], (double)lt);
            __threadfence();
            const unsigned done = atomicAdd(&g_cnt, 1u);
            if (done == gridDim.x - 1) {
                __threadfence();
                const double loss_proj = g_acc[0] / (double)(AA * WW);
                const double loss_tv   = g_acc[1] / (double)((HH - 1) * (WW - 1));
                out[0] = (float)(loss_proj + 0.01 * loss_tv);
            }
        }
    }
}

// ---------------------------------------------------------------------------
extern "C" void kernel_launch(void* const* d_in, const int* in_sizes, int n_in,
                              void* d_out, int out_size) {
    const float* pred     = (const float*)d_in[0];   // [1,512,512]
    const float* sinogram = (const float*)d_in[1];   // [1,180,512]
    const float* angles   = (const float*)d_in[2];   // [180]
    float* out = (float*)d_out;

    const int prep_total = PW * PW;                  // 264,196
    prep_kernel<<<(prep_total + 255) / 256, 256>>>(pred);

    dim3 rgrid(AA, NSPLIT);                          // 180 x 2 = 360 blocks
    radon_kernel<<<rgrid, 512>>>(angles);

    loss_kernel<<<256, 256>>>(pred, sinogram, out);
}

// round 4
// speedup vs baseline: 1.6544x; 1.6544x over previous
#include <cuda_runtime.h>
#include <math.h>

#define HH 512
#define WW 512
#define AA 180
#define GST 516             // global padded row stride (floats, 16B-aligned rows)
#define TST 516             // smem tile row stride (floats)
#define CH 16               // pr rows per chunk
#define NCHUNK 33           // ceil(513 / 16)
#define NSPLIT 4            // chunk-groups (blocks) per angle

// Scratch (device globals; no allocation allowed). 16B alignment makes the
// float4 staging loads contractually legal.
__device__ __align__(16) float g_pimg[514 * GST];  // padded image
__device__ __align__(16) float g_pT[514 * GST];    // padded transposed image
__device__ float  g_sino[AA * WW];    // radon accumulator
__device__ double g_acc[2];           // [0]=sum sq proj diff, [1]=sum tv

// ---------------------------------------------------------------------------
// Kernel 1: build padded + padded-transposed scalar images; zero accumulators.
// g_pimg[r][c] = pred[r-1][c-1] for r,c in [1,512], else 0. g_pT = transpose.
// ---------------------------------------------------------------------------
__global__ void prep_kernel(const float* __restrict__ pred) {
    const int idx = blockIdx.x * blockDim.x + threadIdx.x;
    const int total = 514 * GST;
    if (idx < total) {
        const int r = idx / GST;
        const int c = idx - r * GST;
        float a = 0.0f, b = 0.0f;
        if (r >= 1 && r <= HH && c >= 1 && c <= WW) {
            a = pred[(r - 1) * WW + (c - 1)];
            b = pred[(c - 1) * WW + (r - 1)];
        }
        g_pimg[idx] = a;
        g_pT[idx]   = b;
    }
    if (idx < AA * WW) g_sino[idx] = 0.0f;
    if (idx == 0) { g_acc[0] = 0.0; g_acc[1] = 0.0; }
}

// ---------------------------------------------------------------------------
// Kernel 2: row-chunk-driven radon.
// Effective coords (transpose chosen so |d(iy)/dh| = max(|sin|,|cos|)):
//   iy(j) = iyS + j*cy   (cy = |c| >= 0.707, j enumerates h in iy-increasing order)
//   ix(j) = ixS + j*dxj
// Chunk m owns samples whose padded top row floor(iy)+1 is in [16m, 16m+16);
// rows [R, R+16] are staged in SMEM, gather is 4x LDS.32 per sample.
// ---------------------------------------------------------------------------
__global__ __launch_bounds__(512, 3) void radon_kernel(const float* __restrict__ angles) {
    __shared__ float4 tile4[(CH + 1) * (TST / 4)];   // 17 x 516 floats = 34.3 KB
    float* tile = (float*)tile4;

    const int a = blockIdx.x;
    const int w = threadIdx.x;

    const float ang = angles[a];
    const float sn = sinf(ang);
    const float cs = cosf(ang);
    const bool  swp = fabsf(sn) > fabsf(cs);

    const float c = swp ? -sn : cs;                    // d(iy)/dh, |c| >= 0.7071
    const float d = swp ?  cs : -sn;                   // d(ix)/dh
    const float u = (float)w + 0.5f - 256.0f;
    const float by = fmaf(swp ? cs : sn, u, 255.5f);
    const float bx = fmaf(swp ? sn : cs, u, 255.5f);
    const float* __restrict__ img = swp ? g_pT : g_pimg;

    const float sgn   = (c >= 0.0f) ? 1.0f : -1.0f;
    const float cy    = fabsf(c);
    const float invcy = 1.0f / cy;
    const float iyS   = fmaf(-255.5f, cy, by);         // iy at j=0 (both signs)
    const float dxj   = sgn * d;
    const float ixS   = fmaf(-sgn * 255.5f, d, bx);

    float acc = 0.0f;

    const int c0 = (NCHUNK * blockIdx.y) / NSPLIT;
    const int c1 = (NCHUNK * (blockIdx.y + 1)) / NSPLIT;

    for (int m = c0; m < c1; m++) {
        const int R    = m * CH;
        const int Rend = min(R + CH, 513);
        const int nr   = Rend - R;                     // pr rows owned by chunk
        const int nrows = nr + 1;                      // + bottom row

        // Stage rows R..R+nr (flat float4 copy; GST == TST, rows 16B-aligned)
        {
            const int n4 = nrows * (GST / 4);
            const float4* __restrict__ src = (const float4*)(img + R * GST);
            for (int t = threadIdx.x; t < n4; t += 512)
                tile4[t] = src[t];
        }
        __syncthreads();

        // j-window: iy in [R-1, Rend-1), with safety margin; exact guard below.
        const int jA    = (int)ceilf(((float)(R - 1) - iyS) * invcy) - 1;
        const int trips = (int)((float)nr * invcy) + 3;
        const float jAf = (float)jA;
        const float iy0 = fmaf(jAf, cy, iyS);
        const float ix0 = fmaf(jAf, dxj, ixS);

        #pragma unroll 4
        for (int k = 0; k < trips; k++) {
            const float kf = (float)k;
            const float iy = fmaf(kf, cy, iy0);
            const float ix = fmaf(kf, dxj, ix0);
            const float fy = floorf(iy);
            const float fx = floorf(ix);
            const int prl = (int)fy + 1 - R;           // tile-local top row
            const int pc  = (int)fx + 1;               // padded column
            const unsigned ju = (unsigned)(jA + k);
            if ((unsigned)prl < (unsigned)nr && (unsigned)pc <= 512u && ju < 512u) {
                const float wy = iy - fy;
                const float wx = ix - fx;
                const float* p = tile + prl * TST + pc;
                const float v00 = p[0],   v01 = p[1];
                const float v10 = p[TST], v11 = p[TST + 1];
                const float top = fmaf(wx, v01 - v00, v00);
                const float bot = fmaf(wx, v11 - v10, v10);
                acc += fmaf(wy, bot - top, top);
            }
        }
        __syncthreads();
    }
    atomicAdd(&g_sino[a * WW + w], acc);
}

// ---------------------------------------------------------------------------
// Kernel 3: fused MSE + TV reduction.
// ---------------------------------------------------------------------------
__global__ void loss_kernel(const float* __restrict__ pred,
                            const float* __restrict__ sino_tgt) {
    const int tid    = blockIdx.x * blockDim.x + threadIdx.x;
    const int stride = gridDim.x * blockDim.x;

    float lp = 0.0f;
    for (int i = tid; i < AA * WW; i += stride) {
        const float df = g_sino[i] - sino_tgt[i];
        lp = fmaf(df, df, lp);
    }

    float lt = 0.0f;
    const int TVW = WW - 1, TVH = HH - 1;
    for (int i = tid; i < TVH * TVW; i += stride) {
        const int y = i / TVW;
        const int x = i - y * TVW;
        const float p  = pred[y * WW + x];
        const float dx = pred[y * WW + x + 1] - p;
        const float dy = pred[(y + 1) * WW + x] - p;
        lt += sqrtf(fmaf(dx, dx, fmaf(dy, dy, 1e-8f)));
    }

    for (int off = 16; off > 0; off >>= 1) {
        lp += __shfl_down_sync(0xFFFFFFFFu, lp, off);
        lt += __shfl_down_sync(0xFFFFFFFFu, lt, off);
    }
    __shared__ float s_lp[32], s_lt[32];
    const int lane = threadIdx.x & 31;
    const int warp = threadIdx.x >> 5;
    if (lane == 0) { s_lp[warp] = lp; s_lt[warp] = lt; }
    __syncthreads();
    const int nwarps = blockDim.x >> 5;
    if (warp == 0) {
        lp = (lane < nwarps) ? s_lp[lane] : 0.0f;
        lt = (lane < nwarps) ? s_lt[lane] : 0.0f;
        for (int off = 16; off > 0; off >>= 1) {
            lp += __shfl_down_sync(0xFFFFFFFFu, lp, off);
            lt += __shfl_down_sync(0xFFFFFFFFu, lt, off);
        }
        if (lane == 0) {
            atomicAdd(&g_acc[0], (double)lp);
            atomicAdd(&g_acc[1], (double)lt);
        }
    }
}

__global__ void finalize_kernel(float* __restrict__ out) {
    const double loss_proj = g_acc[0] / (double)(AA * WW);
    const double loss_tv   = g_acc[1] / (double)((HH - 1) * (WW - 1));
    out[0] = (float)(loss_proj + 0.01 * loss_tv);
}

// ---------------------------------------------------------------------------
extern "C" void kernel_launch(void* const* d_in, const int* in_sizes, int n_in,
                              void* d_out, int out_size) {
    const float* pred     = (const float*)d_in[0];   // [1,512,512]
    const float* sinogram = (const float*)d_in[1];   // [1,180,512]
    const float* angles   = (const float*)d_in[2];   // [180]
    float* out = (float*)d_out;

    const int prep_total = 514 * GST;                // 265,224
    prep_kernel<<<(prep_total + 255) / 256, 256>>>(pred);

    dim3 rgrid(AA, NSPLIT);                          // 180 x 4 = 720 blocks
    radon_kernel<<<rgrid, 512>>>(angles);

    loss_kernel<<<148, 256>>>(pred, sinogram);
    finalize_kernel<<<1, 1>>>(out);
}

// round 5
// speedup vs baseline: 1.8907x; 1.1428x over previous
#include <cuda_runtime.h>
#include <cuda_fp16.h>
#include <math.h>

#define HH 512
#define WW 512
#define AA 180
#define TSTH 516            // pair-image row stride (half2 units; 2064 B, 16B-mult)
#define CH 16               // padded top-rows per chunk
#define NCHUNK 33           // ceil(513 / 16)
#define NSPLIT 8            // blocks per angle
#define TILE_H2 ((CH + 1) * TSTH)          // half2 per tile buffer
#define DYN_SMEM (2 * TILE_H2 * 4)         // 70,176 B (double buffer)

// Scratch (device globals; no allocation allowed):
__device__ __align__(16) __half2 g_H[514 * TSTH];   // pair image: (P(r,c), P(r,c+1))
__device__ __align__(16) __half2 g_TH[514 * TSTH];  // transposed pair image
__device__ float  g_sino[AA * WW];
__device__ double g_acc[2];
__device__ unsigned g_cnt;

// ---------------- cp.async helpers ----------------
__device__ __forceinline__ void cp_async16(void* smem, const void* gmem) {
    unsigned s = (unsigned)__cvta_generic_to_shared(smem);
    asm volatile("cp.async.cg.shared.global [%0], [%1], 16;\n" :: "r"(s), "l"(gmem));
}
__device__ __forceinline__ void cp_commit() {
    asm volatile("cp.async.commit_group;\n");
}
template <int N> __device__ __forceinline__ void cp_wait() {
    asm volatile("cp.async.wait_group %0;\n" :: "n"(N));
}

// ---------------------------------------------------------------------------
// Kernel 1a: normal pair image (coalesced) + zero accumulators.
// P(r,c) = pred[r-1][c-1] for r,c in [1,512], else 0.
// ---------------------------------------------------------------------------
__global__ void prep_normal(const float* __restrict__ pred) {
    const int idx = blockIdx.x * blockDim.x + threadIdx.x;
    if (idx < 514 * TSTH) {
        const int r = idx / TSTH;
        const int c = idx - r * TSTH;
        float a = 0.0f, b = 0.0f;
        if (r >= 1 && r <= 512) {
            const float* row = pred + (r - 1) * 512;
            if (c >= 1 && c <= 512) a = row[c - 1];
            if (c <= 511)           b = row[c];
        }
        g_H[idx] = __floats2half2_rn(a, b);
    }
    if (idx < AA * WW) g_sino[idx] = 0.0f;
    if (idx == 0) { g_acc[0] = 0.0; g_acc[1] = 0.0; g_cnt = 0u; }
}

// ---------------------------------------------------------------------------
// Kernel 1b: transposed pair image via SMEM-tiled transpose.
// g_TH[r][c] = (T(r,c), T(r,c+1)), T(r,c) = pred[c-1][r-1] (padded zero).
// ---------------------------------------------------------------------------
__global__ void prep_transpose(const float* __restrict__ pred) {
    __shared__ float s[33][33];        // s[i][j] = pred[c0-1+i][r0-1+j]
    const int r0 = blockIdx.x * 32;
    const int c0 = blockIdx.y * 32;

    for (int t = threadIdx.y * 32 + threadIdx.x; t < 33 * 32; t += 256) {
        const int i = t >> 5, j = t & 31;
        const int sr = c0 - 1 + i;     // pred row
        const int sc = r0 - 1 + j;     // pred col
        float v = 0.0f;
        if ((unsigned)sr < 512u && (unsigned)sc < 512u) v = pred[sr * 512 + sc];
        s[i][j] = v;
    }
    __syncthreads();

    const int i = threadIdx.x;
    #pragma unroll
    for (int k = 0; k < 4; k++) {
        const int j = threadIdx.y + k * 8;
        const int orow = r0 + j, ocol = c0 + i;
        if (orow < 514 && ocol < TSTH)
            g_TH[orow * TSTH + ocol] = __floats2half2_rn(s[i][j], s[i + 1][j]);
    }
}

// ---------------------------------------------------------------------------
// Kernel 2: row-chunk radon, half2-pair SMEM tiles, cp.async double buffer.
// ---------------------------------------------------------------------------
__global__ __launch_bounds__(512, 3) void radon_kernel(const float* __restrict__ angles) {
    extern __shared__ __align__(16) unsigned char dynsmem[];
    __half2* const tbuf0 = (__half2*)dynsmem;
    __half2* const tbuf1 = tbuf0 + TILE_H2;

    const int a = blockIdx.x;
    const int w = threadIdx.x;

    const float ang = angles[a];
    const float sn = sinf(ang);
    const float cs = cosf(ang);
    const bool  swp = fabsf(sn) > fabsf(cs);

    const float c = swp ? -sn : cs;                    // |c| >= 0.7071
    const float d = swp ?  cs : -sn;
    const float u = (float)w + 0.5f - 256.0f;
    const float by = fmaf(swp ? cs : sn, u, 255.5f);
    const float bx = fmaf(swp ? sn : cs, u, 255.5f);
    const __half2* __restrict__ img = swp ? g_TH : g_H;

    const float sgn   = (c >= 0.0f) ? 1.0f : -1.0f;
    const float cy    = fabsf(c);
    const float invcy = 1.0f / cy;
    const float iyS   = fmaf(-255.5f, cy, by);
    const float dxj   = sgn * d;
    const float ixS   = fmaf(-sgn * 255.5f, d, bx);

    const int c0 = (NCHUNK * blockIdx.y) / NSPLIT;
    const int c1 = (NCHUNK * (blockIdx.y + 1)) / NSPLIT;

    // ---- stage chunk m into buffer b (cp.async, 16B granules) ----
    auto stage = [&](int m, __half2* dstbuf) {
        const int R = m * CH;
        const int nrows = min(R + CH, 513) - R + 1;
        const int n16 = nrows * (TSTH / 4);            // float4 count (TSTH/4=129)
        const float4* __restrict__ src = (const float4*)(img + R * TSTH);
        float4* dst = (float4*)dstbuf;
        for (int t = threadIdx.x; t < n16; t += 512)
            cp_async16(&dst[t], &src[t]);
        cp_commit();
    };

    stage(c0, (c0 & 1) ? tbuf1 : tbuf0);

    float acc = 0.0f;

    for (int m = c0; m < c1; m++) {
        if (m + 1 < c1) {
            stage(m + 1, ((m + 1) & 1) ? tbuf1 : tbuf0);
            cp_wait<1>();
        } else {
            cp_wait<0>();
        }
        __syncthreads();

        const int R  = m * CH;
        const int nr = min(R + CH, 513) - R;

        const int jA0   = (int)ceilf(((float)(R - 1) - iyS) * invcy) - 1;
        const int trips = (int)((float)nr * invcy) + 3;
        const int jA    = min(max(jA0, 0), 512 - trips);   // ju guard folded away

        float iy = fmaf((float)jA, cy, iyS);
        float ix = fmaf((float)jA, dxj, ixS);

        const __half2* __restrict__ tb = (m & 1) ? tbuf1 : tbuf0;

        #pragma unroll 4
        for (int k = 0; k < trips; k++) {
            const float fy = floorf(iy);
            const float fx = floorf(ix);
            const int prl = (int)fy + 1 - R;
            const int pc  = (int)fx + 1;
            if ((unsigned)prl < (unsigned)nr && (unsigned)pc <= 512u) {
                const float wy = iy - fy;
                const float wx = ix - fx;
                const __half2* p = tb + prl * TSTH + pc;
                const float2 tv = __half22float2(p[0]);
                const float2 bv = __half22float2(p[TSTH]);
                const float top = fmaf(wx, tv.y - tv.x, tv.x);
                const float bot = fmaf(wx, bv.y - bv.x, bv.x);
                acc += fmaf(wy, bot - top, top);
            }
            iy += cy;
            ix += dxj;
        }
        __syncthreads();
    }
    atomicAdd(&g_sino[a * WW + w], acc);
}

// ---------------------------------------------------------------------------
// Kernel 3: fused MSE + TV reduction + finalize (last block writes out).
// ---------------------------------------------------------------------------
__global__ void loss_kernel(const float* __restrict__ pred,
                            const float* __restrict__ sino_tgt,
                            float* __restrict__ out) {
    const int tid    = blockIdx.x * blockDim.x + threadIdx.x;
    const int stride = gridDim.x * blockDim.x;

    float lp = 0.0f;
    for (int i = tid; i < AA * WW; i += stride) {
        const float df = g_sino[i] - sino_tgt[i];
        lp = fmaf(df, df, lp);
    }

    float lt = 0.0f;
    const int TVW = WW - 1, TVH = HH - 1;
    for (int i = tid; i < TVH * TVW; i += stride) {
        const int y = i / TVW;
        const int x = i - y * TVW;
        const float p  = pred[y * WW + x];
        const float dx = pred[y * WW + x + 1] - p;
        const float dy = pred[(y + 1) * WW + x] - p;
        lt += sqrtf(fmaf(dx, dx, fmaf(dy, dy, 1e-8f)));
    }

    for (int off = 16; off > 0; off >>= 1) {
        lp += __shfl_down_sync(0xFFFFFFFFu, lp, off);
        lt += __shfl_down_sync(0xFFFFFFFFu, lt, off);
    }
    __shared__ float s_lp[32], s_lt[32];
    const int lane = threadIdx.x & 31;
    const int warp = threadIdx.x >> 5;
    if (lane == 0) { s_lp[warp] = lp; s_lt[warp] = lt; }
    __syncthreads();
    const int nwarps = blockDim.x >> 5;
    if (warp == 0) {
        lp = (lane < nwarps) ? s_lp[lane] : 0.0f;
        lt = (lane < nwarps) ? s_lt[lane] : 0.0f;
        for (int off = 16; off > 0; off >>= 1) {
            lp += __shfl_down_sync(0xFFFFFFFFu, lp, off);
            lt += __shfl_down_sync(0xFFFFFFFFu, lt, off);
        }
        if (lane == 0) {
            atomicAdd(&g_acc[0], (double)lp);
            atomicAdd(&g_acc[1], (double)lt);
            __threadfence();
            const unsigned done = atomicAdd(&g_cnt, 1u);
            if (done == gridDim.x - 1) {
                __threadfence();
                const double loss_proj = g_acc[0] / (double)(AA * WW);
                const double loss_tv   = g_acc[1] / (double)((HH - 1) * (WW - 1));
                out[0] = (float)(loss_proj + 0.01 * loss_tv);
            }
        }
    }
}

// ---------------------------------------------------------------------------
extern "C" void kernel_launch(void* const* d_in, const int* in_sizes, int n_in,
                              void* d_out, int out_size) {
    const float* pred     = (const float*)d_in[0];   // [1,512,512]
    const float* sinogram = (const float*)d_in[1];   // [1,180,512]
    const float* angles   = (const float*)d_in[2];   // [180]
    float* out = (float*)d_out;

    cudaFuncSetAttribute(radon_kernel,
                         cudaFuncAttributeMaxDynamicSharedMemorySize, DYN_SMEM);

    const int prep_total = 514 * TSTH;               // 265,224
    prep_normal<<<(prep_total + 255) / 256, 256>>>(pred);

    dim3 tgrid(17, 17);                              // 544x544 coverage of 514x516
    prep_transpose<<<tgrid, dim3(32, 8)>>>(pred);

    dim3 rgrid(AA, NSPLIT);                          // 180 x 8 = 1440 blocks
    radon_kernel<<<rgrid, 512, DYN_SMEM>>>(angles);

    loss_kernel<<<148, 256>>>(pred, sinogram, out);
}

// round 6
// speedup vs baseline: 2.1961x; 1.1616x over previous
#include <cuda_runtime.h>
#include <cuda_fp16.h>
#include <math.h>

#define HH 512
#define WW 512
#define AA 180
#define TST 516             // pair-image row stride in half2 (2064 B/row)
#define CH 16               // padded top-rows per chunk
#define NCHUNK 33           // ceil(513 / 16)
#define NSPLIT 10           // blocks per angle -> 1800 blocks = 4.05 waves
#define TILE_H2 (CH * TST)  // 8256 half2 = 33,024 B per buffer
#define DYN_SMEM (2 * TILE_H2 * 4)   // 66,048 B

// Vertical-pair images: g_V[y*TST+s] = half2(P(y,s-1), P(y+1,s-1)),
// P(r,c) = pred[r-1][c-1] inside [1,512]^2 else 0. y in [0,513), s in [0,516).
// Columns s=0,1,514,515 are (0,0) guard columns by construction.
__device__ __align__(16) __half2 g_V[513 * TST];
__device__ __align__(16) __half2 g_VT[513 * TST];   // transposed orientation
__device__ float  g_sino[AA * WW];
__device__ double g_acc[2];
__device__ unsigned g_cnt;

// ---------------- cp.async helpers ----------------
__device__ __forceinline__ void cp_async16(void* smem, const void* gmem) {
    unsigned s = (unsigned)__cvta_generic_to_shared(smem);
    asm volatile("cp.async.cg.shared.global [%0], [%1], 16;\n" :: "r"(s), "l"(gmem));
}
__device__ __forceinline__ void cp_commit() {
    asm volatile("cp.async.commit_group;\n");
}
template <int N> __device__ __forceinline__ void cp_wait() {
    asm volatile("cp.async.wait_group %0;\n" :: "n"(N));
}

// ---------------------------------------------------------------------------
// Kernel 1a: normal vertical-pair image (coalesced) + zero accumulators.
// ---------------------------------------------------------------------------
__global__ void prep_normal(const float* __restrict__ pred) {
    const int y = blockIdx.x;          // 0..512
    const int s = threadIdx.x;         // 0..543
    if (s < TST) {
        float a = 0.0f, b = 0.0f;
        if (s >= 2 && s <= 513) {
            const int pc = s - 2;                       // pred col
            if (y >= 1 && y <= 512) a = pred[(y - 1) * 512 + pc];
            if (y <= 511)           b = pred[y * 512 + pc];
        }
        g_V[y * TST + s] = __floats2half2_rn(a, b);
    }
    const int gid = blockIdx.x * blockDim.x + threadIdx.x;
    if (gid < AA * WW) g_sino[gid] = 0.0f;
    if (gid == 0) { g_acc[0] = 0.0; g_acc[1] = 0.0; g_cnt = 0u; }
}

// ---------------------------------------------------------------------------
// Kernel 1b: transposed vertical-pair image via SMEM tile.
// g_VT[y][s] = half2(pred[s-2][y-1], pred[s-2][y]) (guarded zeros).
// ---------------------------------------------------------------------------
__global__ void prep_transpose(const float* __restrict__ pred) {
    __shared__ float t[32][35];        // t[i][j] = pred[s0-2+i][y0-1+j], padded stride
    const int s0 = blockIdx.x * 32;
    const int y0 = blockIdx.y * 32;
    const int tx = threadIdx.x;        // 0..31
    const int ty = threadIdx.y;        // 0..7

    for (int i = ty; i < 32; i += 8) {
        const int pr = s0 - 2 + i;
        {
            const int pc = y0 - 1 + tx;
            t[i][tx] = ((unsigned)pr < 512u && (unsigned)pc < 512u)
                       ? pred[pr * 512 + pc] : 0.0f;
        }
        if (tx < 2) {
            const int pc = y0 + 31 + tx;
            t[i][32 + tx] = ((unsigned)pr < 512u && (unsigned)pc < 512u)
                            ? pred[pr * 512 + pc] : 0.0f;
        }
    }
    __syncthreads();

    for (int j = ty; j < 32; j += 8) {
        const int y = y0 + j;
        const int s = s0 + tx;
        if (y < 513 && s < TST)
            g_VT[y * TST + s] = __floats2half2_rn(t[tx][j], t[tx][j + 1]);
    }
}

// ---------------------------------------------------------------------------
// Kernel 2: row-chunk radon, vertical-pair tiles, fp16 horizontal lerp,
// cp.async double buffer. blockIdx.x = angle, blockIdx.y = chunk group.
// ---------------------------------------------------------------------------
__global__ __launch_bounds__(512, 3) void radon_kernel(const float* __restrict__ angles) {
    extern __shared__ __align__(16) unsigned char dynsmem[];
    __half2* const tbuf0 = (__half2*)dynsmem;
    __half2* const tbuf1 = tbuf0 + TILE_H2;

    const int a = blockIdx.x;
    const int w = threadIdx.x;

    const float ang = angles[a];
    const float sn = sinf(ang);
    const float cs = cosf(ang);
    const bool  swp = fabsf(sn) > fabsf(cs);

    const float c = swp ? -sn : cs;                    // |c| >= 0.7071
    const float d = swp ?  cs : -sn;
    const float u = (float)w + 0.5f - 256.0f;
    const float by = fmaf(swp ? cs : sn, u, 255.5f);
    const float bx = fmaf(swp ? sn : cs, u, 255.5f);
    const __half2* __restrict__ img = swp ? g_VT : g_V;

    const float sgn   = (c >= 0.0f) ? 1.0f : -1.0f;
    const float cy    = fabsf(c);
    const float invcy = 1.0f / cy;
    const float iyS   = fmaf(-255.5f, cy, by);         // iy at j=0
    const float dxj   = sgn * d;
    const float ixS   = fmaf(-sgn * 255.5f, d, bx);

    const int c0 = (NCHUNK * blockIdx.y) / NSPLIT;
    const int c1 = (NCHUNK * (blockIdx.y + 1)) / NSPLIT;

    auto stage = [&](int m, __half2* dstbuf) {
        const int R  = m * CH;
        const int nr = min(R + CH, 513) - R;
        const int n16 = nr * (TST / 4);                // float4 per tile (129/row)
        const float4* __restrict__ src = (const float4*)(img + R * TST);
        float4* dst = (float4*)dstbuf;
        for (int t = threadIdx.x; t < n16; t += 512)
            cp_async16(&dst[t], &src[t]);
        cp_commit();
    };

    stage(c0, (c0 & 1) ? tbuf1 : tbuf0);

    float acc = 0.0f;

    for (int m = c0; m < c1; m++) {
        if (m + 1 < c1) {
            stage(m + 1, ((m + 1) & 1) ? tbuf1 : tbuf0);
            cp_wait<1>();
        } else {
            cp_wait<0>();
        }
        __syncthreads();

        const int R  = m * CH;
        const int nr = min(R + CH, 513) - R;

        const int jA0   = (int)ceilf(((float)(R - 1) - iyS) * invcy) - 1;
        const int trips = (int)((float)nr * invcy) + 3;
        const int jA    = min(max(jA0, 0), 512 - trips);

        float iy_loc = fmaf((float)jA, cy,  iyS) - (float)(R - 1);  // prl = floor
        float ix_loc = fmaf((float)jA, dxj, ixS) + 2.0f;            // s   = floor

        const __half2* __restrict__ tb = (m & 1) ? tbuf1 : tbuf0;

        #pragma unroll 4
        for (int k = 0; k < trips; k++) {
            const int yi = __float2int_rd(iy_loc);
            if ((unsigned)yi < (unsigned)nr) {         // ownership (exact as R5)
                const float wy = iy_loc - (float)yi;
                const int   si0 = __float2int_rd(ix_loc);
                const float wx  = ix_loc - (float)si0;
                const int   si  = min(max(si0, 0), 514);   // exact via guard cols
                const __half2 wx2 = __float2half2_rn(wx);
                const __half2* p = tb + yi * TST + si;
                const __half2 A = p[0];                // (v00, v10)
                const __half2 B = p[1];                // (v01, v11)
                const __half2 mm = __hfma2(wx2, __hsub2(B, A), A);   // (top, bot)
                const float top = __low2float(mm);
                const float bot = __high2float(mm);
                acc += fmaf(wy, bot - top, top);
            }
            iy_loc += cy;
            ix_loc += dxj;
        }
        __syncthreads();
    }
    atomicAdd(&g_sino[a * WW + w], acc);
}

// ---------------------------------------------------------------------------
// Kernel 3: fused MSE + TV reduction + finalize (last block writes out).
// ---------------------------------------------------------------------------
__global__ void loss_kernel(const float* __restrict__ pred,
                            const float* __restrict__ sino_tgt,
                            float* __restrict__ out) {
    const int tid    = blockIdx.x * blockDim.x + threadIdx.x;
    const int stride = gridDim.x * blockDim.x;

    float lp = 0.0f;
    for (int i = tid; i < AA * WW; i += stride) {
        const float df = g_sino[i] - sino_tgt[i];
        lp = fmaf(df, df, lp);
    }

    float lt = 0.0f;
    const int TVW = WW - 1, TVH = HH - 1;
    for (int i = tid; i < TVH * TVW; i += stride) {
        const int y = i / TVW;
        const int x = i - y * TVW;
        const float p  = pred[y * WW + x];
        const float dx = pred[y * WW + x + 1] - p;
        const float dy = pred[(y + 1) * WW + x] - p;
        lt += sqrtf(fmaf(dx, dx, fmaf(dy, dy, 1e-8f)));
    }

    for (int off = 16; off > 0; off >>= 1) {
        lp += __shfl_down_sync(0xFFFFFFFFu, lp, off);
        lt += __shfl_down_sync(0xFFFFFFFFu, lt, off);
    }
    __shared__ float s_lp[32], s_lt[32];
    const int lane = threadIdx.x & 31;
    const int warp = threadIdx.x >> 5;
    if (lane == 0) { s_lp[warp] = lp; s_lt[warp] = lt; }
    __syncthreads();
    const int nwarps = blockDim.x >> 5;
    if (warp == 0) {
        lp = (lane < nwarps) ? s_lp[lane] : 0.0f;
        lt = (lane < nwarps) ? s_lt[lane] : 0.0f;
        for (int off = 16; off > 0; off >>= 1) {
            lp += __shfl_down_sync(0xFFFFFFFFu, lp, off);
            lt += __shfl_down_sync(0xFFFFFFFFu, lt, off);
        }
        if (lane == 0) {
            atomicAdd(&g_acc[0], (double)lp);
            atomicAdd(&g_acc[1], (double)lt);
            __threadfence();
            const unsigned done = atomicAdd(&g_cnt, 1u);
            if (done == gridDim.x - 1) {
                __threadfence();
                const double loss_proj = g_acc[0] / (double)(AA * WW);
                const double loss_tv   = g_acc[1] / (double)((HH - 1) * (WW - 1));
                out[0] = (float)(loss_proj + 0.01 * loss_tv);
            }
        }
    }
}

// ---------------------------------------------------------------------------
extern "C" void kernel_launch(void* const* d_in, const int* in_sizes, int n_in,
                              void* d_out, int out_size) {
    const float* pred     = (const float*)d_in[0];   // [1,512,512]
    const float* sinogram = (const float*)d_in[1];   // [1,180,512]
    const float* angles   = (const float*)d_in[2];   // [180]
    float* out = (float*)d_out;

    cudaFuncSetAttribute(radon_kernel,
                         cudaFuncAttributeMaxDynamicSharedMemorySize, DYN_SMEM);

    prep_normal<<<513, 544>>>(pred);

    dim3 tgrid(17, 17);
    prep_transpose<<<tgrid, dim3(32, 8)>>>(pred);

    dim3 rgrid(AA, NSPLIT);                          // 180 x 10 = 1800 blocks
    radon_kernel<<<rgrid, 512, DYN_SMEM>>>(angles);

    loss_kernel<<<592, 256>>>(pred, sinogram, out);
}